// round 3
// baseline (speedup 1.0000x reference)
#include <cuda_runtime.h>
#include <math.h>

// Problem shape (fixed): B=4, N=10000, E=32, C=128, O=128
#define BB 4
#define NN 10000
#define BN 40000        // B*N
#define CC 128
#define OO 128
#define EE 32

// Scratch (device globals — allocation-free rule)
__device__ float g_A[(size_t)BN * OO];      // x @ (Wt - Wb) + bias
__device__ float g_P[(size_t)BN * OO];      // x @ Wb
__device__ float g_Wc[CC * 2 * OO];         // [128][256] combined weight: [Wt-Wb | Wb]
__device__ int   g_idx64;                   // 1 if edge_index is int64, 0 if int32

// ---------------------------------------------------------------------------
// Detect edge_index dtype: int64 values are (-1..9999) so the high 32-bit word
// must be the sign extension of the low word. For int32 data the "high words"
// are other random indices; 64 consecutive matches is impossible (~1e-128).
// ---------------------------------------------------------------------------
__global__ void detect_kernel(const int* __restrict__ e32) {
    int ok = 1;
    for (int i = 0; i < 64; i++) {
        int lo = e32[2 * i];
        int hi = e32[2 * i + 1];
        int want = (lo < 0) ? -1 : 0;
        if (lo < -1 || lo >= NN || hi != want) { ok = 0; break; }
    }
    g_idx64 = ok;
}

// ---------------------------------------------------------------------------
// Build combined weight Wc[k][0:128] = Wt[k] - Wb[k], Wc[k][128:256] = Wb[k]
// W layout: [2C, O] row-major, Wt = W[0:128], Wb = W[128:256]
// ---------------------------------------------------------------------------
__global__ void prep_kernel(const float* __restrict__ W) {
    int k = blockIdx.x;       // 0..127
    int o = threadIdx.x;      // 0..255
    float v;
    if (o < OO) {
        v = W[k * OO + o] - W[(k + CC) * OO + o];
    } else {
        v = W[(k + CC) * OO + (o - OO)];
    }
    g_Wc[k * 256 + o] = v;
}

// ---------------------------------------------------------------------------
// GEMM: [BN x 128] @ [128 x 256] -> A (cols 0:128, +bias), P (cols 128:256)
// CTA tile: 64 rows x 256 cols, 256 threads, thread tile 8x8, K-chunks of 32.
// BN = 40000 = 625 * 64 exactly, so no row-bound checks needed.
// ---------------------------------------------------------------------------
__global__ __launch_bounds__(256) void gemm_kernel(const float* __restrict__ x,
                                                   const float* __restrict__ bias) {
    __shared__ float xs[32][68];    // [k][row], padded: float4-aligned rows, low conflicts
    __shared__ float ws[32][256];   // [k][col]

    const int tid = threadIdx.x;
    const int tx = tid & 31;        // col group (0..31) -> cols tx*8..tx*8+7
    const int ty = tid >> 5;        // row group (0..7)  -> rows ty*8..ty*8+7
    const int rowbase = blockIdx.x * 64;

    float acc[8][8];
#pragma unroll
    for (int i = 0; i < 8; i++)
#pragma unroll
        for (int j = 0; j < 8; j++) acc[i][j] = 0.f;

    for (int kc = 0; kc < CC; kc += 32) {
        // load x tile (64 rows x 32 k), transposed into xs[k][row]
#pragma unroll
        for (int i = 0; i < 8; i++) {
            int li = tid + i * 256;           // 0..2047
            int row = li >> 5;                // 0..63
            int k = li & 31;                  // 0..31
            xs[k][row] = x[(size_t)(rowbase + row) * CC + kc + k];
        }
        // load W tile (32 k x 256 cols)
#pragma unroll
        for (int i = 0; i < 32; i++) {
            int li = tid + i * 256;           // 0..8191
            int k = li >> 8;                  // 0..31
            int col = li & 255;               // 0..255
            ws[k][col] = g_Wc[(kc + k) * 256 + col];
        }
        __syncthreads();

#pragma unroll
        for (int k = 0; k < 32; k++) {
            float xr[8], wc[8];
#pragma unroll
            for (int i = 0; i < 8; i++) xr[i] = xs[k][ty * 8 + i];
#pragma unroll
            for (int j = 0; j < 8; j++) wc[j] = ws[k][tx * 8 + j];
#pragma unroll
            for (int i = 0; i < 8; i++)
#pragma unroll
                for (int j = 0; j < 8; j++)
                    acc[i][j] = fmaf(xr[i], wc[j], acc[i][j]);
        }
        __syncthreads();
    }

    const int colbase = tx * 8;
    if (colbase < OO) {
        // A part: add bias
        float bb[8];
#pragma unroll
        for (int j = 0; j < 8; j++) bb[j] = bias[colbase + j];
#pragma unroll
        for (int i = 0; i < 8; i++) {
            int gr = rowbase + ty * 8 + i;
#pragma unroll
            for (int j = 0; j < 8; j++)
                g_A[(size_t)gr * OO + colbase + j] = acc[i][j] + bb[j];
        }
    } else {
        // P part
#pragma unroll
        for (int i = 0; i < 8; i++) {
            int gr = rowbase + ty * 8 + i;
#pragma unroll
            for (int j = 0; j < 8; j++)
                g_P[(size_t)gr * OO + (colbase - OO) + j] = acc[i][j];
        }
    }
}

// ---------------------------------------------------------------------------
// Gather-max + elu epilogue. One warp per node.
// Each lane owns 4 output channels (float4). Lane e holds edge e's index;
// broadcast via shfl; gather P rows (512B, fully coalesced float4/lane),
// running max; finally out = elu(A + max) or -inf if no valid edges.
// ---------------------------------------------------------------------------
__device__ __forceinline__ float elu1(float v) {
    return v > 0.f ? v : expm1f(v);
}

__global__ __launch_bounds__(256) void gather_kernel(const void* __restrict__ eidx,
                                                     float* __restrict__ out) {
    const int gw = (blockIdx.x * 256 + threadIdx.x) >> 5;   // node row (b*N+n)
    const int lane = threadIdx.x & 31;
    if (gw >= BN) return;

    const int b = gw / NN;
    const int bbase = b * NN;

    const float4* __restrict__ A4 = (const float4*)g_A;
    const float4* __restrict__ P4 = (const float4*)g_P;

    int myidx;
    if (g_idx64) {
        myidx = (int)((const long long*)eidx)[(size_t)gw * EE + lane];
    } else {
        myidx = ((const int*)eidx)[(size_t)gw * EE + lane];
    }
    const unsigned vm = __ballot_sync(0xffffffffu, myidx >= 0);

    float4 m = make_float4(-INFINITY, -INFINITY, -INFINITY, -INFINITY);
#pragma unroll
    for (int e = 0; e < EE; e++) {
        int j = __shfl_sync(0xffffffffu, myidx, e);
        if (j >= 0) {
            float4 p = P4[(size_t)(bbase + j) * 32 + lane];
            m.x = fmaxf(m.x, p.x);
            m.y = fmaxf(m.y, p.y);
            m.z = fmaxf(m.z, p.z);
            m.w = fmaxf(m.w, p.w);
        }
    }

    float4 o;
    if (vm == 0u) {
        o = make_float4(-INFINITY, -INFINITY, -INFINITY, -INFINITY);
    } else {
        float4 a = A4[(size_t)gw * 32 + lane];
        o.x = elu1(a.x + m.x);
        o.y = elu1(a.y + m.y);
        o.z = elu1(a.z + m.z);
        o.w = elu1(a.w + m.w);
    }
    reinterpret_cast<float4*>(out)[(size_t)gw * 32 + lane] = o;
}

// ---------------------------------------------------------------------------
// Launch
// ---------------------------------------------------------------------------
extern "C" void kernel_launch(void* const* d_in, const int* in_sizes, int n_in,
                              void* d_out, int out_size) {
    (void)in_sizes; (void)n_in; (void)out_size;
    const float* x    = (const float*)d_in[0];   // [B,N,C] fp32
    const void*  eidx = d_in[1];                 // [B,N,E] int64 or int32
    const float* W    = (const float*)d_in[2];   // [2C,O] fp32
    const float* bias = (const float*)d_in[3];   // [O] fp32
    float* out = (float*)d_out;                  // [B,N,O] fp32

    detect_kernel<<<1, 1>>>((const int*)eidx);
    prep_kernel<<<CC, 256>>>(W);
    gemm_kernel<<<BN / 64, 256>>>(x, bias);
    gather_kernel<<<BN / 8, 256>>>(eidx, out);
}

// round 5
// speedup vs baseline: 1.1359x; 1.1359x over previous
#include <cuda_runtime.h>
#include <cuda_bf16.h>
#include <math.h>
#include <stdint.h>

// Problem shape (fixed): B=4, N=10000, E=32, C=128, O=128
#define BB 4
#define NN 10000
#define BN 40000        // B*N
#define CC 128
#define OO 128
#define EE 32
#define MTILE 128
#define NTILES 313      // ceil(40000 / 128)

// ---------------------------------------------------------------------------
// Scratch (device globals — allocation-free rule)
// ---------------------------------------------------------------------------
__device__ float g_A[(size_t)BN * OO];                 // x @ (Wt - Wb) + bias
__device__ float g_P[(size_t)BN * OO];                 // x @ Wb
__device__ __nv_bfloat16 g_Bhi[256 * CC];              // B^T[n][k] hi part
__device__ __nv_bfloat16 g_Blo[256 * CC];              // B^T[n][k] lo part
__device__ int   g_idx64;                              // edge_index is int64?

__device__ __forceinline__ uint32_t smem_u32(const void* p) {
    uint32_t a;
    asm("{ .reg .u64 t; cvta.to.shared.u64 t, %1; cvt.u32.u64 %0, t; }" : "=r"(a) : "l"(p));
    return a;
}
__device__ __forceinline__ uint32_t pack_bf16(float a, float b) {
    __nv_bfloat162 p = __floats2bfloat162_rn(a, b);
    return *reinterpret_cast<uint32_t*>(&p);
}

#define LDSM_X4(r0, r1, r2, r3, a) \
    asm volatile("ldmatrix.sync.aligned.m8n8.x4.shared.b16 {%0,%1,%2,%3}, [%4];" \
                 : "=r"(r0), "=r"(r1), "=r"(r2), "=r"(r3) : "r"(a))

#define MMA16816(c, a0, a1, a2, a3, b0, b1) \
    asm volatile("mma.sync.aligned.m16n8k16.row.col.f32.bf16.bf16.f32 " \
                 "{%0,%1,%2,%3}, {%4,%5,%6,%7}, {%8,%9}, {%0,%1,%2,%3};" \
                 : "+f"((c)[0]), "+f"((c)[1]), "+f"((c)[2]), "+f"((c)[3]) \
                 : "r"(a0), "r"(a1), "r"(a2), "r"(a3), "r"(b0), "r"(b1))

// SMEM layout (dynamic).  Row stride 272B: 272 mod 128 = 16 -> 8 consecutive
// rows hit 8 distinct 16B chunks => conflict-free ldmatrix.
#define ROWB   272
#define SM_AHI 0
#define SM_ALO (MTILE * ROWB)                  // 34816
#define SM_BHI (2 * MTILE * ROWB)              // 69632
#define SM_BLO (SM_BHI + 256 * ROWB)           // 139264
#define SM_BIAS (SM_BLO + 256 * ROWB)          // 208896
#define SMEM_SZ (SM_BIAS + 512)                // 209408

// ---------------------------------------------------------------------------
// Detect edge_index dtype (parallel). For int64 data each 64-bit value is in
// (-1..9999): high word == sign-extension of low word, 64 consecutive times.
// ---------------------------------------------------------------------------
__global__ void detect_kernel(const int* __restrict__ e32) {
    int lane = threadIdx.x;
    int ok = 1;
    for (int i = lane; i < 64; i += 32) {
        int lo = e32[2 * i];
        int hi = e32[2 * i + 1];
        int want = (lo < 0) ? -1 : 0;
        if (lo < -1 || lo >= NN || hi != want) ok = 0;
    }
    unsigned b = __ballot_sync(0xffffffffu, ok);
    if (lane == 0) g_idx64 = (b == 0xffffffffu) ? 1 : 0;
}

// ---------------------------------------------------------------------------
// Build B^T[n][k] hi/lo bf16:  Wc[k][n] = n<128 ? Wt-Wb : Wb
// ---------------------------------------------------------------------------
__global__ void prep_b_kernel(const float* __restrict__ W) {
    int n = blockIdx.x;    // 0..255 (output column)
    int k = threadIdx.x;   // 0..127 (reduction index)
    float v;
    if (n < OO) v = W[k * OO + n] - W[(k + CC) * OO + n];
    else        v = W[(k + CC) * OO + (n - OO)];
    __nv_bfloat16 h = __float2bfloat16(v);
    float l = v - __bfloat162float(h);
    g_Bhi[n * CC + k] = h;
    g_Blo[n * CC + k] = __float2bfloat16(l);
}

// ---------------------------------------------------------------------------
// Tensor-core GEMM via mma.sync (HMMA): [BN x 128] fp32, bf16 3-product split.
// CTA: 512 threads, tile 128 x 256, K resident. Warp grid 4x4, warp m32 x n64.
// cols 0:128 -> g_A (+bias), cols 128:256 -> g_P.
// ---------------------------------------------------------------------------
__global__ __launch_bounds__(512, 1) void gemm_kernel(const float* __restrict__ x,
                                                      const float* __restrict__ bias) {
    extern __shared__ char smem[];
    const uint32_t sb = smem_u32(smem);
    const int tid  = threadIdx.x;
    const int wid  = tid >> 5;
    const int lane = tid & 31;
    const int rowbase = blockIdx.x * MTILE;

    // ---- load + hi/lo-convert x tile (128 rows x 128 k) ----
    {
        const int row = tid >> 2;          // 0..127
        const int q   = tid & 3;           // 4 threads per row
        const int m   = rowbase + row;
        #pragma unroll
        for (int i = 0; i < 8; i++) {
            const int c4 = q * 32 + i * 4; // float col
            float4 v = make_float4(0.f, 0.f, 0.f, 0.f);
            if (m < BN) v = *(const float4*)(x + (size_t)m * CC + c4);
            float h0 = __bfloat162float(__float2bfloat16(v.x));
            float h1 = __bfloat162float(__float2bfloat16(v.y));
            float h2 = __bfloat162float(__float2bfloat16(v.z));
            float h3 = __bfloat162float(__float2bfloat16(v.w));
            uint32_t hw0 = pack_bf16(h0, h1), hw1 = pack_bf16(h2, h3);
            uint32_t lw0 = pack_bf16(v.x - h0, v.y - h1);
            uint32_t lw1 = pack_bf16(v.z - h2, v.w - h3);
            uint32_t off = row * ROWB + c4 * 2;
            asm volatile("st.shared.v2.b32 [%0], {%1, %2};"
                         :: "r"(sb + SM_AHI + off), "r"(hw0), "r"(hw1) : "memory");
            asm volatile("st.shared.v2.b32 [%0], {%1, %2};"
                         :: "r"(sb + SM_ALO + off), "r"(lw0), "r"(lw1) : "memory");
        }
    }
    // ---- load B^T hi/lo (256 rows x 128 k each) ----
    {
        const uint4* __restrict__ shi = (const uint4*)g_Bhi;  // 16 uint4 per row
        const uint4* __restrict__ slo = (const uint4*)g_Blo;
        #pragma unroll
        for (int t = 0; t < 8; t++) {
            int idx = tid + t * 512;       // 0..4095
            int r = idx >> 4;
            int c = idx & 15;
            *(uint4*)(smem + SM_BHI + r * ROWB + c * 16) = shi[idx];
            *(uint4*)(smem + SM_BLO + r * ROWB + c * 16) = slo[idx];
        }
    }
    if (tid < OO) ((float*)(smem + SM_BIAS))[tid] = bias[tid];
    __syncthreads();

    // ---- MMA mainloop ----
    const int wr = wid >> 2;               // warp row 0..3 -> rows wr*32
    const int wc = wid & 3;                // warp col 0..3 -> cols wc*64

    float acc[2][8][4];
    #pragma unroll
    for (int mi = 0; mi < 2; mi++)
        #pragma unroll
        for (int ni = 0; ni < 8; ni++)
            #pragma unroll
            for (int r = 0; r < 4; r++) acc[mi][ni][r] = 0.f;

    // ldmatrix base addresses (k-offset added per step)
    // A x4: lanes 0-15 -> rows (wr*32 + mi*16 + l), k bytes +0; lanes 16-31 -> same rows, +16
    const uint32_t a_base = sb + (wr * 32 + (lane & 15)) * ROWB + (lane >> 4) * 16;
    // B x4: group g = lane>>3: n = wc*64 + j*16 + (g>>1)*8 + (lane&7), kbyte = (g&1)*16
    const uint32_t b_base = sb + SM_BHI +
        (wc * 64 + ((lane >> 4) & 1) * 8 + (lane & 7)) * ROWB + (((lane >> 3) & 1) * 16);

    const uint32_t aplane[3] = {0u, (uint32_t)SM_ALO, 0u};
    const uint32_t bplane[3] = {0u, 0u, (uint32_t)(SM_BLO - SM_BHI)};

    #pragma unroll
    for (int p = 0; p < 3; p++) {
        const uint32_t ab = a_base + aplane[p];
        const uint32_t bb = b_base + bplane[p];
        #pragma unroll
        for (int kk = 0; kk < 8; kk++) {
            const uint32_t kby = kk * 32;
            uint32_t a0[4], a1[4];
            LDSM_X4(a0[0], a0[1], a0[2], a0[3], ab + kby);
            LDSM_X4(a1[0], a1[1], a1[2], a1[3], ab + 16 * ROWB + kby);
            uint32_t b[4][4];   // [j][4]: regs 0,1 -> n-tile 2j ; 2,3 -> n-tile 2j+1
            #pragma unroll
            for (int j = 0; j < 4; j++)
                LDSM_X4(b[j][0], b[j][1], b[j][2], b[j][3], bb + j * 16 * ROWB + kby);
            #pragma unroll
            for (int j = 0; j < 4; j++) {
                MMA16816(acc[0][2 * j + 0], a0[0], a0[1], a0[2], a0[3], b[j][0], b[j][1]);
                MMA16816(acc[0][2 * j + 1], a0[0], a0[1], a0[2], a0[3], b[j][2], b[j][3]);
                MMA16816(acc[1][2 * j + 0], a1[0], a1[1], a1[2], a1[3], b[j][0], b[j][1]);
                MMA16816(acc[1][2 * j + 1], a1[0], a1[1], a1[2], a1[3], b[j][2], b[j][3]);
            }
        }
    }

    // ---- epilogue: fragment -> global (cols<128: A + bias, else P) ----
    {
        const float* sbias = (const float*)(smem + SM_BIAS);
        const int g = lane >> 2;           // group id (row within 8)
        const int t = lane & 3;            // thread in group (col pair)
        #pragma unroll
        for (int mi = 0; mi < 2; mi++) {
            #pragma unroll
            for (int half = 0; half < 2; half++) {
                const int m = rowbase + wr * 32 + mi * 16 + g + half * 8;
                if (m >= BN) continue;
                #pragma unroll
                for (int ni = 0; ni < 8; ni++) {
                    const int col = wc * 64 + ni * 8 + t * 2;
                    float c0 = acc[mi][ni][half * 2 + 0];
                    float c1 = acc[mi][ni][half * 2 + 1];
                    if (col < OO) {
                        float2 o = make_float2(c0 + sbias[col], c1 + sbias[col + 1]);
                        *(float2*)(g_A + (size_t)m * OO + col) = o;
                    } else {
                        float2 o = make_float2(c0, c1);
                        *(float2*)(g_P + (size_t)m * OO + (col - OO)) = o;
                    }
                }
            }
        }
    }
}

// ---------------------------------------------------------------------------
// Gather-max + elu epilogue. One warp per node (36.7us in R3 profile).
// ---------------------------------------------------------------------------
__device__ __forceinline__ float elu1(float v) {
    return v > 0.f ? v : expm1f(v);
}

__global__ __launch_bounds__(256) void gather_kernel(const void* __restrict__ eidx,
                                                     float* __restrict__ out) {
    const int gw = (blockIdx.x * 256 + threadIdx.x) >> 5;   // node row (b*N+n)
    const int lane = threadIdx.x & 31;
    if (gw >= BN) return;

    const int b = gw / NN;
    const int bbase = b * NN;

    const float4* __restrict__ A4 = (const float4*)g_A;
    const float4* __restrict__ P4 = (const float4*)g_P;

    int myidx;
    if (g_idx64) {
        myidx = (int)((const long long*)eidx)[(size_t)gw * EE + lane];
    } else {
        myidx = ((const int*)eidx)[(size_t)gw * EE + lane];
    }
    const unsigned vm = __ballot_sync(0xffffffffu, myidx >= 0);

    float4 m = make_float4(-INFINITY, -INFINITY, -INFINITY, -INFINITY);
    #pragma unroll
    for (int e = 0; e < EE; e++) {
        int j = __shfl_sync(0xffffffffu, myidx, e);
        if (j >= 0) {
            float4 p = P4[(size_t)(bbase + j) * 32 + lane];
            m.x = fmaxf(m.x, p.x);
            m.y = fmaxf(m.y, p.y);
            m.z = fmaxf(m.z, p.z);
            m.w = fmaxf(m.w, p.w);
        }
    }

    float4 o;
    if (vm == 0u) {
        o = make_float4(-INFINITY, -INFINITY, -INFINITY, -INFINITY);
    } else {
        float4 a = A4[(size_t)gw * 32 + lane];
        o.x = elu1(a.x + m.x);
        o.y = elu1(a.y + m.y);
        o.z = elu1(a.z + m.z);
        o.w = elu1(a.w + m.w);
    }
    reinterpret_cast<float4*>(out)[(size_t)gw * 32 + lane] = o;
}

// ---------------------------------------------------------------------------
// Launch
// ---------------------------------------------------------------------------
extern "C" void kernel_launch(void* const* d_in, const int* in_sizes, int n_in,
                              void* d_out, int out_size) {
    (void)in_sizes; (void)n_in; (void)out_size;
    const float* x    = (const float*)d_in[0];   // [B,N,C] fp32
    const void*  eidx = d_in[1];                 // [B,N,E] int64 or int32
    const float* W    = (const float*)d_in[2];   // [2C,O] fp32
    const float* bias = (const float*)d_in[3];   // [O] fp32
    float* out = (float*)d_out;                  // [B,N,O] fp32

    cudaFuncSetAttribute(gemm_kernel, cudaFuncAttributeMaxDynamicSharedMemorySize, SMEM_SZ);

    detect_kernel<<<1, 32>>>((const int*)eidx);
    prep_b_kernel<<<256, 128>>>(W);
    gemm_kernel<<<NTILES, 512, SMEM_SZ>>>(x, bias);
    gather_kernel<<<BN / 8, 256>>>(eidx, out);
}

// round 9
// speedup vs baseline: 1.5558x; 1.3696x over previous
#include <cuda_runtime.h>
#include <cuda_fp16.h>
#include <math.h>
#include <stdint.h>

// Problem shape (fixed): B=4, N=10000, E=32, C=128, O=128
#define NN 10000
#define BN 40000        // B*N
#define CC 128
#define OO 128
#define EE 32
#define MT 64           // rows per GEMM tile
#define TILES 625       // 40000 / 64 exactly
#define GEMM_GRID 296   // 2 CTAs per SM

// ---------------------------------------------------------------------------
// Scratch (device globals — allocation-free rule)
// ---------------------------------------------------------------------------
__device__ float g_A[(size_t)BN * OO];     // x @ (Wt - Wb) + bias
__device__ float g_P[(size_t)BN * OO];     // x @ Wb
__device__ __half g_Bh[256 * CC];          // B^T[n][k] = Wc[k][n] in fp16
__device__ int   g_idx64;                  // edge_index is int64?

__device__ __forceinline__ uint32_t smem_u32(const void* p) {
    uint32_t a;
    asm("{ .reg .u64 t; cvta.to.shared.u64 t, %1; cvt.u32.u64 %0, t; }" : "=r"(a) : "l"(p));
    return a;
}
__device__ __forceinline__ uint32_t pack_h2(float a, float b) {
    __half2 p = __floats2half2_rn(a, b);
    return *reinterpret_cast<uint32_t*>(&p);
}

#define LDSM_X4(r0, r1, r2, r3, a) \
    asm volatile("ldmatrix.sync.aligned.m8n8.x4.shared.b16 {%0,%1,%2,%3}, [%4];" \
                 : "=r"(r0), "=r"(r1), "=r"(r2), "=r"(r3) : "r"(a))

#define MMA16816(c, a0, a1, a2, a3, b0, b1) \
    asm volatile("mma.sync.aligned.m16n8k16.row.col.f32.f16.f16.f32 " \
                 "{%0,%1,%2,%3}, {%4,%5,%6,%7}, {%8,%9}, {%0,%1,%2,%3};" \
                 : "+f"((c)[0]), "+f"((c)[1]), "+f"((c)[2]), "+f"((c)[3]) \
                 : "r"(a0), "r"(a1), "r"(a2), "r"(a3), "r"(b0), "r"(b1))

// SMEM layout. Row stride 272B (272 mod 128 = 16 -> conflict-free ldmatrix).
#define ROWB   272
#define SM_AH  0                          // 64 x 272 = 17408 (x_hi)
#define SM_AL  17408                      // 64 x 272 (x_lo)
#define SM_BH  34816                      // 256 x 272 = 69632 (w_hi)
#define SM_BIAS 104448                    // 128 floats
#define SMEM_SZ 104960                    // <= 113.5KB -> 2 CTAs/SM

// ---------------------------------------------------------------------------
// prep: blocks 0..255 build B^T fp16; block 256 detects edge_index dtype.
// ---------------------------------------------------------------------------
__global__ void prep_kernel(const float* __restrict__ W, const int* __restrict__ e32) {
    if (blockIdx.x == 256) {
        // int64 values are in (-1..9999): high word == sign-ext of low word.
        if (threadIdx.x < 32) {
            int lane = threadIdx.x;
            int ok = 1;
            for (int i = lane; i < 64; i += 32) {
                int lo = e32[2 * i];
                int hi = e32[2 * i + 1];
                int want = (lo < 0) ? -1 : 0;
                if (lo < -1 || lo >= NN || hi != want) ok = 0;
            }
            unsigned b = __ballot_sync(0xffffffffu, ok);
            if (lane == 0) g_idx64 = (b == 0xffffffffu) ? 1 : 0;
        }
        return;
    }
    int n = blockIdx.x;    // 0..255 (output column)
    int k = threadIdx.x;   // 0..127 (reduction index)
    float v;
    if (n < OO) v = W[k * OO + n] - W[(k + CC) * OO + n];   // Wt - Wb
    else        v = W[(k + CC) * OO + (n - OO)];            // Wb
    g_Bh[n * CC + k] = __float2half_rn(v);
}

// ---------------------------------------------------------------------------
// Persistent HMMA GEMM: [BN x 128] fp32 -> fp16 2-product split -> [BN x 256]
// CTA: 256 threads, tile 64 x 256 (2 CTAs/SM). Warp grid 2x4, warp m32 x n64.
// cols 0:128 -> g_A (+bias), cols 128:256 -> g_P.
// ---------------------------------------------------------------------------
__global__ __launch_bounds__(256, 2) void gemm_kernel(const float* __restrict__ x,
                                                      const float* __restrict__ bias) {
    extern __shared__ char smem[];
    const uint32_t sb = smem_u32(smem);
    const int tid  = threadIdx.x;
    const int wid  = tid >> 5;
    const int lane = tid & 31;

    // ---- one-time: load B^T fp16 plane (64KB) + bias ----
    {
        const uint4* __restrict__ src = (const uint4*)g_Bh;  // 16 uint4 per 256B row
        #pragma unroll
        for (int t = 0; t < 16; t++) {
            int idx = tid + t * 256;       // 0..4095
            int r = idx >> 4;
            int c = idx & 15;
            *(uint4*)(smem + SM_BH + r * ROWB + c * 16) = src[idx];
        }
        if (tid < OO) ((float*)(smem + SM_BIAS))[tid] = bias[tid];
    }

    const int wr = wid >> 2;               // warp row 0..1 -> rows wr*32
    const int wc = wid & 3;                // warp col 0..3 -> cols wc*64

    // ldmatrix base addresses (k-offset added per step)
    const uint32_t a_base = sb + (wr * 32 + (lane & 15)) * ROWB + (lane >> 4) * 16;
    const uint32_t b_base = sb + SM_BH +
        (wc * 64 + ((lane >> 4) & 1) * 8 + (lane & 7)) * ROWB + (((lane >> 3) & 1) * 16);

    for (int tile = blockIdx.x; tile < TILES; tile += GEMM_GRID) {
        const int rowbase = tile * MT;

        // ---- load + fp16 hi/lo-convert x tile (64 rows x 128 k) ----
        #pragma unroll
        for (int i = 0; i < 8; i++) {
            int f = i * 256 + tid;            // float4 index, 0..2047
            int row = f >> 5;                 // 0..63
            int c4 = f & 31;                  // 0..31 (float4 within row)
            float4 v = *(const float4*)(x + (size_t)(rowbase + row) * CC + c4 * 4);
            __half h0 = __float2half_rn(v.x), h1 = __float2half_rn(v.y);
            __half h2 = __float2half_rn(v.z), h3 = __float2half_rn(v.w);
            uint32_t hw0 = pack_h2(__half2float(h0), __half2float(h1));
            uint32_t hw1 = pack_h2(__half2float(h2), __half2float(h3));
            uint32_t lw0 = pack_h2(v.x - __half2float(h0), v.y - __half2float(h1));
            uint32_t lw1 = pack_h2(v.z - __half2float(h2), v.w - __half2float(h3));
            uint32_t off = row * ROWB + c4 * 8;
            asm volatile("st.shared.v2.b32 [%0], {%1, %2};"
                         :: "r"(sb + SM_AH + off), "r"(hw0), "r"(hw1) : "memory");
            asm volatile("st.shared.v2.b32 [%0], {%1, %2};"
                         :: "r"(sb + SM_AL + off), "r"(lw0), "r"(lw1) : "memory");
        }
        __syncthreads();

        // ---- MMA: 2 planes (x_hi, x_lo) x 8 k16-steps ----
        float acc[2][8][4];
        #pragma unroll
        for (int mi = 0; mi < 2; mi++)
            #pragma unroll
            for (int ni = 0; ni < 8; ni++)
                #pragma unroll
                for (int r = 0; r < 4; r++) acc[mi][ni][r] = 0.f;

        #pragma unroll
        for (int p = 0; p < 2; p++) {
            const uint32_t ab = a_base + (p ? (SM_AL - SM_AH) : 0u);
            #pragma unroll
            for (int kk = 0; kk < 8; kk++) {
                const uint32_t kby = kk * 32;
                uint32_t a0[4], a1[4];
                LDSM_X4(a0[0], a0[1], a0[2], a0[3], ab + kby);
                LDSM_X4(a1[0], a1[1], a1[2], a1[3], ab + 16 * ROWB + kby);
                uint32_t b[4][4];
                #pragma unroll
                for (int j = 0; j < 4; j++)
                    LDSM_X4(b[j][0], b[j][1], b[j][2], b[j][3], b_base + j * 16 * ROWB + kby);
                #pragma unroll
                for (int j = 0; j < 4; j++) {
                    MMA16816(acc[0][2 * j + 0], a0[0], a0[1], a0[2], a0[3], b[j][0], b[j][1]);
                    MMA16816(acc[0][2 * j + 1], a0[0], a0[1], a0[2], a0[3], b[j][2], b[j][3]);
                    MMA16816(acc[1][2 * j + 0], a1[0], a1[1], a1[2], a1[3], b[j][0], b[j][1]);
                    MMA16816(acc[1][2 * j + 1], a1[0], a1[1], a1[2], a1[3], b[j][2], b[j][3]);
                }
            }
        }

        // ---- epilogue: fragment -> global (cols<128: A + bias, else P) ----
        {
            const float* sbias = (const float*)(smem + SM_BIAS);
            const int g = lane >> 2;
            const int t = lane & 3;
            #pragma unroll
            for (int mi = 0; mi < 2; mi++) {
                #pragma unroll
                for (int half = 0; half < 2; half++) {
                    const int m = rowbase + wr * 32 + mi * 16 + g + half * 8;
                    #pragma unroll
                    for (int ni = 0; ni < 8; ni++) {
                        const int col = wc * 64 + ni * 8 + t * 2;
                        float c0 = acc[mi][ni][half * 2 + 0];
                        float c1 = acc[mi][ni][half * 2 + 1];
                        if (col < OO) {
                            float2 o = make_float2(c0 + sbias[col], c1 + sbias[col + 1]);
                            *(float2*)(g_A + (size_t)m * OO + col) = o;
                        } else {
                            float2 o = make_float2(c0, c1);
                            *(float2*)(g_P + (size_t)m * OO + (col - OO)) = o;
                        }
                    }
                }
            }
        }
        __syncthreads();   // A-plane smem free before next tile's convert
    }
}

// ---------------------------------------------------------------------------
// Gather-max + elu epilogue. One warp per node; 4 independent max
// accumulators so 4 LDG.128 stay in flight per iteration.
// ---------------------------------------------------------------------------
__device__ __forceinline__ float elu1(float v) {
    return v > 0.f ? v : expm1f(v);
}
__device__ __forceinline__ void max4(float4& m, float4 p) {
    m.x = fmaxf(m.x, p.x); m.y = fmaxf(m.y, p.y);
    m.z = fmaxf(m.z, p.z); m.w = fmaxf(m.w, p.w);
}

__global__ __launch_bounds__(256) void gather_kernel(const void* __restrict__ eidx,
                                                     float* __restrict__ out) {
    const int gw = (blockIdx.x * 256 + threadIdx.x) >> 5;   // node row (b*N+n)
    const int lane = threadIdx.x & 31;
    if (gw >= BN) return;

    const int b = gw / NN;
    const int bbase = b * NN;

    const float4* __restrict__ A4 = (const float4*)g_A;
    const float4* __restrict__ base = (const float4*)g_P + (size_t)bbase * 32 + lane;

    int myidx;
    if (g_idx64) {
        myidx = (int)((const long long*)eidx)[(size_t)gw * EE + lane];
    } else {
        myidx = ((const int*)eidx)[(size_t)gw * EE + lane];
    }
    const unsigned vm = __ballot_sync(0xffffffffu, myidx >= 0);

    float4 a = A4[(size_t)gw * 32 + lane];   // prefetch early

    const float4 ninf = make_float4(-INFINITY, -INFINITY, -INFINITY, -INFINITY);
    float4 m0 = ninf, m1 = ninf, m2 = ninf, m3 = ninf;

    #pragma unroll
    for (int e = 0; e < EE; e += 4) {
        int j0 = __shfl_sync(0xffffffffu, myidx, e + 0);
        int j1 = __shfl_sync(0xffffffffu, myidx, e + 1);
        int j2 = __shfl_sync(0xffffffffu, myidx, e + 2);
        int j3 = __shfl_sync(0xffffffffu, myidx, e + 3);
        if (j0 >= 0) { float4 p = base[j0 * 32]; max4(m0, p); }
        if (j1 >= 0) { float4 p = base[j1 * 32]; max4(m1, p); }
        if (j2 >= 0) { float4 p = base[j2 * 32]; max4(m2, p); }
        if (j3 >= 0) { float4 p = base[j3 * 32]; max4(m3, p); }
    }
    max4(m0, m1); max4(m2, m3); max4(m0, m2);

    float4 o;
    if (vm == 0u) {
        o = ninf;
    } else {
        o.x = elu1(a.x + m0.x);
        o.y = elu1(a.y + m0.y);
        o.z = elu1(a.z + m0.z);
        o.w = elu1(a.w + m0.w);
    }
    reinterpret_cast<float4*>(out)[(size_t)gw * 32 + lane] = o;
}

// ---------------------------------------------------------------------------
// Launch
// ---------------------------------------------------------------------------
extern "C" void kernel_launch(void* const* d_in, const int* in_sizes, int n_in,
                              void* d_out, int out_size) {
    (void)in_sizes; (void)n_in; (void)out_size;
    const float* x    = (const float*)d_in[0];   // [B,N,C] fp32
    const void*  eidx = d_in[1];                 // [B,N,E] int64 or int32
    const float* W    = (const float*)d_in[2];   // [2C,O] fp32
    const float* bias = (const float*)d_in[3];   // [O] fp32
    float* out = (float*)d_out;                  // [B,N,O] fp32

    cudaFuncSetAttribute(gemm_kernel, cudaFuncAttributeMaxDynamicSharedMemorySize, SMEM_SZ);

    prep_kernel<<<257, 128>>>(W, (const int*)eidx);
    gemm_kernel<<<GEMM_GRID, 256, SMEM_SZ>>>(x, bias);
    gather_kernel<<<BN / 8, 256>>>(eidx, out);
}

// round 13
// speedup vs baseline: 1.9680x; 1.2650x over previous
#include <cuda_runtime.h>
#include <cuda_fp16.h>
#include <math.h>
#include <stdint.h>

// Problem shape (fixed): B=4, N=10000, E=32, C=128, O=128
#define NN 10000
#define BN 40000        // B*N
#define CC 128
#define OO 128
#define EE 32
#define MT 64           // rows per GEMM tile
#define TILES 625       // 40000 / 64 exactly
#define GEMM_GRID 296   // 2 CTAs per SM

// ---------------------------------------------------------------------------
// Scratch (device globals — allocation-free rule)
// ---------------------------------------------------------------------------
__device__ float  g_A[(size_t)BN * OO];     // x @ (Wt - Wb) + bias   (fp32)
__device__ __half g_Ph[(size_t)BN * OO];    // x @ Wb                 (fp16)
__device__ __half g_Bh[256 * CC];           // B^T[n][k] = Wc[k][n] fp16
__device__ int    g_idx64;                  // edge_index is int64?

__device__ __forceinline__ uint32_t smem_u32(const void* p) {
    uint32_t a;
    asm("{ .reg .u64 t; cvta.to.shared.u64 t, %1; cvt.u32.u64 %0, t; }" : "=r"(a) : "l"(p));
    return a;
}
__device__ __forceinline__ uint32_t pack_h2(float a, float b) {
    __half2 p = __floats2half2_rn(a, b);
    return *reinterpret_cast<uint32_t*>(&p);
}

#define LDSM_X4(r0, r1, r2, r3, a) \
    asm volatile("ldmatrix.sync.aligned.m8n8.x4.shared.b16 {%0,%1,%2,%3}, [%4];" \
                 : "=r"(r0), "=r"(r1), "=r"(r2), "=r"(r3) : "r"(a))

#define MMA16816(c, a0, a1, a2, a3, b0, b1) \
    asm volatile("mma.sync.aligned.m16n8k16.row.col.f32.f16.f16.f32 " \
                 "{%0,%1,%2,%3}, {%4,%5,%6,%7}, {%8,%9}, {%0,%1,%2,%3};" \
                 : "+f"((c)[0]), "+f"((c)[1]), "+f"((c)[2]), "+f"((c)[3]) \
                 : "r"(a0), "r"(a1), "r"(a2), "r"(a3), "r"(b0), "r"(b1))

// SMEM layout. Row stride 272B (272 mod 128 = 16 -> conflict-free ldmatrix).
#define ROWB   272
#define SM_AH  0                          // 64 x 272 = 17408 (x_hi)
#define SM_AL  17408                      // 64 x 272 (x_lo)
#define SM_BH  34816                      // 256 x 272 = 69632 (w_hi)
#define SM_BIAS 104448                    // 128 floats
#define SMEM_SZ 104960                    // <= 113.5KB -> 2 CTAs/SM

// ---------------------------------------------------------------------------
// prep: blocks 0..7 build B^T fp16 (coalesced reads, smem transpose, packed
// 32B writes); block 8 detects edge_index dtype.
// ---------------------------------------------------------------------------
__global__ __launch_bounds__(256) void prep_kernel(const float* __restrict__ W,
                                                   const int* __restrict__ e32) {
    if (blockIdx.x == 8) {
        // int64 values are in (-1..9999): high word == sign-ext of low word.
        if (threadIdx.x < 32) {
            int lane = threadIdx.x;
            int ok = 1;
            for (int i = lane; i < 64; i += 32) {
                int lo = e32[2 * i];
                int hi = e32[2 * i + 1];
                int want = (lo < 0) ? -1 : 0;
                if (lo < -1 || lo >= NN || hi != want) ok = 0;
            }
            unsigned b = __ballot_sync(0xffffffffu, ok);
            if (lane == 0) g_idx64 = (b == 0xffffffffu) ? 1 : 0;
        }
        return;
    }
    __shared__ uint32_t sh[16][257];
    const int kb = blockIdx.x * 16;
    const int n = threadIdx.x;            // 0..255 (output column)
    #pragma unroll
    for (int ki = 0; ki < 16; ki++) {
        int k = kb + ki;
        float v;
        if (n < OO) v = W[k * OO + n] - W[(k + CC) * OO + n];   // Wt - Wb
        else        v = W[(k + CC) * OO + (n - OO)];            // Wb
        __half h = __float2half_rn(v);
        sh[ki][n] = (uint32_t)*reinterpret_cast<uint16_t*>(&h);
    }
    __syncthreads();
    uint32_t pk[8];
    #pragma unroll
    for (int i = 0; i < 8; i++)
        pk[i] = (sh[2 * i][n] & 0xFFFFu) | (sh[2 * i + 1][n] << 16);
    uint4* dst = (uint4*)((char*)g_Bh + n * 256 + kb * 2);
    dst[0] = make_uint4(pk[0], pk[1], pk[2], pk[3]);
    dst[1] = make_uint4(pk[4], pk[5], pk[6], pk[7]);
}

// ---------------------------------------------------------------------------
// Persistent HMMA GEMM: [BN x 128] fp32 -> fp16 2-product split -> [BN x 256]
// CTA: 256 threads, tile 64 x 256 (2 CTAs/SM). Warp grid 2x4, warp m32 x n64.
// cols 0:128 -> g_A fp32 (+bias), cols 128:256 -> g_Ph fp16.
// ---------------------------------------------------------------------------
__global__ __launch_bounds__(256, 2) void gemm_kernel(const float* __restrict__ x,
                                                      const float* __restrict__ bias) {
    extern __shared__ char smem[];
    const uint32_t sb = smem_u32(smem);
    const int tid  = threadIdx.x;
    const int wid  = tid >> 5;
    const int lane = tid & 31;

    // ---- one-time: load B^T fp16 plane (64KB) + bias ----
    {
        const uint4* __restrict__ src = (const uint4*)g_Bh;  // 16 uint4 per 256B row
        #pragma unroll
        for (int t = 0; t < 16; t++) {
            int idx = tid + t * 256;       // 0..4095
            int r = idx >> 4;
            int c = idx & 15;
            *(uint4*)(smem + SM_BH + r * ROWB + c * 16) = src[idx];
        }
        if (tid < OO) ((float*)(smem + SM_BIAS))[tid] = bias[tid];
    }

    const int wr = wid >> 2;               // warp row 0..1 -> rows wr*32
    const int wc = wid & 3;                // warp col 0..3 -> cols wc*64

    // ldmatrix base addresses (k-offset added per step)
    const uint32_t a_base = sb + (wr * 32 + (lane & 15)) * ROWB + (lane >> 4) * 16;
    const uint32_t b_base = sb + SM_BH +
        (wc * 64 + ((lane >> 4) & 1) * 8 + (lane & 7)) * ROWB + (((lane >> 3) & 1) * 16);

    for (int tile = blockIdx.x; tile < TILES; tile += GEMM_GRID) {
        const int rowbase = tile * MT;

        // ---- load + fp16 hi/lo-convert x tile (64 rows x 128 k) ----
        #pragma unroll
        for (int i = 0; i < 8; i++) {
            int f = i * 256 + tid;            // float4 index, 0..2047
            int row = f >> 5;                 // 0..63
            int c4 = f & 31;                  // 0..31 (float4 within row)
            float4 v = *(const float4*)(x + (size_t)(rowbase + row) * CC + c4 * 4);
            __half h0 = __float2half_rn(v.x), h1 = __float2half_rn(v.y);
            __half h2 = __float2half_rn(v.z), h3 = __float2half_rn(v.w);
            uint32_t hw0 = pack_h2(__half2float(h0), __half2float(h1));
            uint32_t hw1 = pack_h2(__half2float(h2), __half2float(h3));
            uint32_t lw0 = pack_h2(v.x - __half2float(h0), v.y - __half2float(h1));
            uint32_t lw1 = pack_h2(v.z - __half2float(h2), v.w - __half2float(h3));
            uint32_t off = row * ROWB + c4 * 8;
            asm volatile("st.shared.v2.b32 [%0], {%1, %2};"
                         :: "r"(sb + SM_AH + off), "r"(hw0), "r"(hw1) : "memory");
            asm volatile("st.shared.v2.b32 [%0], {%1, %2};"
                         :: "r"(sb + SM_AL + off), "r"(lw0), "r"(lw1) : "memory");
        }
        __syncthreads();

        // ---- MMA: 2 planes (x_hi, x_lo) x 8 k16-steps ----
        float acc[2][8][4];
        #pragma unroll
        for (int mi = 0; mi < 2; mi++)
            #pragma unroll
            for (int ni = 0; ni < 8; ni++)
                #pragma unroll
                for (int r = 0; r < 4; r++) acc[mi][ni][r] = 0.f;

        #pragma unroll
        for (int p = 0; p < 2; p++) {
            const uint32_t ab = a_base + (p ? (SM_AL - SM_AH) : 0u);
            #pragma unroll
            for (int kk = 0; kk < 8; kk++) {
                const uint32_t kby = kk * 32;
                uint32_t a0[4], a1[4];
                LDSM_X4(a0[0], a0[1], a0[2], a0[3], ab + kby);
                LDSM_X4(a1[0], a1[1], a1[2], a1[3], ab + 16 * ROWB + kby);
                uint32_t b[4][4];
                #pragma unroll
                for (int j = 0; j < 4; j++)
                    LDSM_X4(b[j][0], b[j][1], b[j][2], b[j][3], b_base + j * 16 * ROWB + kby);
                #pragma unroll
                for (int j = 0; j < 4; j++) {
                    MMA16816(acc[0][2 * j + 0], a0[0], a0[1], a0[2], a0[3], b[j][0], b[j][1]);
                    MMA16816(acc[0][2 * j + 1], a0[0], a0[1], a0[2], a0[3], b[j][2], b[j][3]);
                    MMA16816(acc[1][2 * j + 0], a1[0], a1[1], a1[2], a1[3], b[j][0], b[j][1]);
                    MMA16816(acc[1][2 * j + 1], a1[0], a1[1], a1[2], a1[3], b[j][2], b[j][3]);
                }
            }
        }

        // ---- epilogue: cols<128 -> g_A fp32 (+bias); cols>=128 -> g_Ph fp16 ----
        {
            const float* sbias = (const float*)(smem + SM_BIAS);
            const int g = lane >> 2;
            const int t = lane & 3;
            #pragma unroll
            for (int mi = 0; mi < 2; mi++) {
                #pragma unroll
                for (int half = 0; half < 2; half++) {
                    const int m = rowbase + wr * 32 + mi * 16 + g + half * 8;
                    #pragma unroll
                    for (int ni = 0; ni < 8; ni++) {
                        const int col = wc * 64 + ni * 8 + t * 2;
                        float c0 = acc[mi][ni][half * 2 + 0];
                        float c1 = acc[mi][ni][half * 2 + 1];
                        if (col < OO) {
                            float2 o = make_float2(c0 + sbias[col], c1 + sbias[col + 1]);
                            *(float2*)(g_A + (size_t)m * OO + col) = o;
                        } else {
                            __half2 h = __floats2half2_rn(c0, c1);
                            *(__half2*)(g_Ph + (size_t)m * OO + (col - OO)) = h;
                        }
                    }
                }
            }
        }
        __syncthreads();   // A-plane smem free before next tile's convert
    }
}

// ---------------------------------------------------------------------------
// Gather-max + elu epilogue. One warp per node; fp16 P rows (256B/row),
// 8 independent half2 max accumulators, 4 LDG.64 in flight per iteration.
// ---------------------------------------------------------------------------
__device__ __forceinline__ float elu1(float v) {
    return v > 0.f ? v : expm1f(v);
}

__global__ __launch_bounds__(256) void gather_kernel(const void* __restrict__ eidx,
                                                     float* __restrict__ out) {
    const int gw = (blockIdx.x * 256 + threadIdx.x) >> 5;   // node row (b*N+n)
    const int lane = threadIdx.x & 31;
    if (gw >= BN) return;

    const int b = gw / NN;
    const int bbase = b * NN;

    const float4* __restrict__ A4 = (const float4*)g_A;
    const __half* __restrict__ Pb = g_Ph + (size_t)bbase * OO + lane * 4;

    int myidx;
    if (g_idx64) {
        myidx = (int)((const long long*)eidx)[(size_t)gw * EE + lane];
    } else {
        myidx = ((const int*)eidx)[(size_t)gw * EE + lane];
    }
    const unsigned vm = __ballot_sync(0xffffffffu, myidx >= 0);

    float4 a = A4[(size_t)gw * 32 + lane];   // prefetch early

    const __half2 ninf2 = __floats2half2_rn(-INFINITY, -INFINITY);
    __half2 m0a = ninf2, m0b = ninf2, m1a = ninf2, m1b = ninf2;
    __half2 m2a = ninf2, m2b = ninf2, m3a = ninf2, m3b = ninf2;

    #pragma unroll
    for (int e = 0; e < EE; e += 4) {
        int j0 = __shfl_sync(0xffffffffu, myidx, e + 0);
        int j1 = __shfl_sync(0xffffffffu, myidx, e + 1);
        int j2 = __shfl_sync(0xffffffffu, myidx, e + 2);
        int j3 = __shfl_sync(0xffffffffu, myidx, e + 3);
        if (j0 >= 0) {
            uint2 r = *(const uint2*)(Pb + (size_t)j0 * OO);
            m0a = __hmax2(m0a, *reinterpret_cast<__half2*>(&r.x));
            m0b = __hmax2(m0b, *reinterpret_cast<__half2*>(&r.y));
        }
        if (j1 >= 0) {
            uint2 r = *(const uint2*)(Pb + (size_t)j1 * OO);
            m1a = __hmax2(m1a, *reinterpret_cast<__half2*>(&r.x));
            m1b = __hmax2(m1b, *reinterpret_cast<__half2*>(&r.y));
        }
        if (j2 >= 0) {
            uint2 r = *(const uint2*)(Pb + (size_t)j2 * OO);
            m2a = __hmax2(m2a, *reinterpret_cast<__half2*>(&r.x));
            m2b = __hmax2(m2b, *reinterpret_cast<__half2*>(&r.y));
        }
        if (j3 >= 0) {
            uint2 r = *(const uint2*)(Pb + (size_t)j3 * OO);
            m3a = __hmax2(m3a, *reinterpret_cast<__half2*>(&r.x));
            m3b = __hmax2(m3b, *reinterpret_cast<__half2*>(&r.y));
        }
    }
    m0a = __hmax2(__hmax2(m0a, m1a), __hmax2(m2a, m3a));
    m0b = __hmax2(__hmax2(m0b, m1b), __hmax2(m2b, m3b));

    float4 o;
    if (vm == 0u) {
        o = make_float4(-INFINITY, -INFINITY, -INFINITY, -INFINITY);
    } else {
        float2 fa = __half22float2(m0a);
        float2 fb = __half22float2(m0b);
        o.x = elu1(a.x + fa.x);
        o.y = elu1(a.y + fa.y);
        o.z = elu1(a.z + fb.x);
        o.w = elu1(a.w + fb.y);
    }
    reinterpret_cast<float4*>(out)[(size_t)gw * 32 + lane] = o;
}

// ---------------------------------------------------------------------------
// Launch
// ---------------------------------------------------------------------------
extern "C" void kernel_launch(void* const* d_in, const int* in_sizes, int n_in,
                              void* d_out, int out_size) {
    (void)in_sizes; (void)n_in; (void)out_size;
    const float* x    = (const float*)d_in[0];   // [B,N,C] fp32
    const void*  eidx = d_in[1];                 // [B,N,E] int64 or int32
    const float* W    = (const float*)d_in[2];   // [2C,O] fp32
    const float* bias = (const float*)d_in[3];   // [O] fp32
    float* out = (float*)d_out;                  // [B,N,O] fp32

    cudaFuncSetAttribute(gemm_kernel, cudaFuncAttributeMaxDynamicSharedMemorySize, SMEM_SZ);

    prep_kernel<<<9, 256>>>(W, (const int*)eidx);
    gemm_kernel<<<GEMM_GRID, 256, SMEM_SZ>>>(x, bias);
    gather_kernel<<<BN / 8, 256>>>(eidx, out);
}

// round 14
// speedup vs baseline: 2.9740x; 1.5111x over previous
#include <cuda_runtime.h>
#include <cuda_fp16.h>
#include <math.h>
#include <stdint.h>

// Problem shape (fixed): B=4, N=10000, E=32, C=128, O=128
#define NN 10000
#define BN 40000        // B*N
#define CC 128
#define OO 128
#define EE 32
#define MT 64           // rows per GEMM tile
#define TILES 625       // 40000 / 64 exactly
#define GEMM_GRID 296   // 2 CTAs per SM

// ---------------------------------------------------------------------------
// Scratch (device globals — allocation-free rule)
// ---------------------------------------------------------------------------
__device__ float  g_A[(size_t)BN * OO];     // x @ (Wt - Wb) + bias   (fp32)
__device__ __half g_Ph[(size_t)BN * OO];    // x @ Wb                 (fp16)
__device__ __half g_Bh[256 * CC];           // B^T[n][k] = Wc[k][n] fp16
__device__ int    g_idx64;                  // edge_index is int64?

__device__ __forceinline__ uint32_t smem_u32(const void* p) {
    uint32_t a;
    asm("{ .reg .u64 t; cvta.to.shared.u64 t, %1; cvt.u32.u64 %0, t; }" : "=r"(a) : "l"(p));
    return a;
}

#define LDSM_X4(r0, r1, r2, r3, a) \
    asm volatile("ldmatrix.sync.aligned.m8n8.x4.shared.b16 {%0,%1,%2,%3}, [%4];" \
                 : "=r"(r0), "=r"(r1), "=r"(r2), "=r"(r3) : "r"(a))

#define MMA16816(c, a0, a1, a2, a3, b0, b1) \
    asm volatile("mma.sync.aligned.m16n8k16.row.col.f32.f16.f16.f32 " \
                 "{%0,%1,%2,%3}, {%4,%5,%6,%7}, {%8,%9}, {%0,%1,%2,%3};" \
                 : "+f"((c)[0]), "+f"((c)[1]), "+f"((c)[2]), "+f"((c)[3]) \
                 : "r"(a0), "r"(a1), "r"(a2), "r"(a3), "r"(b0), "r"(b1))

// SMEM layout. Row stride 272B (272 mod 128 = 16 -> conflict-free ldmatrix).
#define ROWB   272
#define SM_A   0                          // 64 x 272 = 17408 (x fp16)
#define SM_B   17408                      // 256 x 272 = 69632 (w fp16)
#define SM_BIAS 87040                     // 128 floats
#define SMEM_SZ 87552                     // 2 CTAs/SM

// ---------------------------------------------------------------------------
// prep: blocks 0..31 build B^T fp16 (4 k-rows each; coalesced reads, smem
// transpose, packed 8B writes); block 32 detects edge_index dtype.
// ---------------------------------------------------------------------------
__global__ __launch_bounds__(256) void prep_kernel(const float* __restrict__ W,
                                                   const int* __restrict__ e32) {
    if (blockIdx.x == 32) {
        // int64 values are in (-1..9999): high word == sign-ext of low word.
        if (threadIdx.x < 32) {
            int lane = threadIdx.x;
            int ok = 1;
            for (int i = lane; i < 64; i += 32) {
                int lo = e32[2 * i];
                int hi = e32[2 * i + 1];
                int want = (lo < 0) ? -1 : 0;
                if (lo < -1 || lo >= NN || hi != want) ok = 0;
            }
            unsigned b = __ballot_sync(0xffffffffu, ok);
            if (lane == 0) g_idx64 = (b == 0xffffffffu) ? 1 : 0;
        }
        return;
    }
    __shared__ uint32_t sh[4][257];
    const int kb = blockIdx.x * 4;
    const int n = threadIdx.x;            // 0..255 (output column)
    #pragma unroll
    for (int ki = 0; ki < 4; ki++) {
        int k = kb + ki;
        float v;
        if (n < OO) v = W[k * OO + n] - W[(k + CC) * OO + n];   // Wt - Wb
        else        v = W[(k + CC) * OO + (n - OO)];            // Wb
        __half h = __float2half_rn(v);
        sh[ki][n] = (uint32_t)*reinterpret_cast<uint16_t*>(&h);
    }
    __syncthreads();
    uint32_t p0 = (sh[0][n] & 0xFFFFu) | (sh[1][n] << 16);
    uint32_t p1 = (sh[2][n] & 0xFFFFu) | (sh[3][n] << 16);
    *(uint2*)((char*)g_Bh + n * 256 + kb * 2) = make_uint2(p0, p1);
}

// ---------------------------------------------------------------------------
// Persistent HMMA GEMM: [BN x 128] fp32 -> fp16 (single plane) -> [BN x 256]
// CTA: 256 threads, tile 64 x 256 (2 CTAs/SM). Warp grid 2x4, warp m32 x n64.
// cols 0:128 -> g_A fp32 (+bias), cols 128:256 -> g_Ph fp16.
// ---------------------------------------------------------------------------
__global__ __launch_bounds__(256, 2) void gemm_kernel(const float* __restrict__ x,
                                                      const float* __restrict__ bias) {
    extern __shared__ char smem[];
    const uint32_t sb = smem_u32(smem);
    const int tid  = threadIdx.x;
    const int wid  = tid >> 5;
    const int lane = tid & 31;

    // ---- one-time: load B^T fp16 plane (64KB) + bias ----
    {
        const uint4* __restrict__ src = (const uint4*)g_Bh;  // 16 uint4 per 256B row
        #pragma unroll
        for (int t = 0; t < 16; t++) {
            int idx = tid + t * 256;       // 0..4095
            int r = idx >> 4;
            int c = idx & 15;
            *(uint4*)(smem + SM_B + r * ROWB + c * 16) = src[idx];
        }
        if (tid < OO) ((float*)(smem + SM_BIAS))[tid] = bias[tid];
    }

    const int wr = wid >> 2;               // warp row 0..1 -> rows wr*32
    const int wc = wid & 3;                // warp col 0..3 -> cols wc*64

    // ldmatrix base addresses (k-offset added per step)
    const uint32_t a_base = sb + SM_A + (wr * 32 + (lane & 15)) * ROWB + (lane >> 4) * 16;
    const uint32_t b_base = sb + SM_B +
        (wc * 64 + ((lane >> 4) & 1) * 8 + (lane & 7)) * ROWB + (((lane >> 3) & 1) * 16);

    for (int tile = blockIdx.x; tile < TILES; tile += GEMM_GRID) {
        const int rowbase = tile * MT;

        // ---- load + fp16-convert x tile (64 rows x 128 k) ----
        #pragma unroll
        for (int i = 0; i < 8; i++) {
            int f = i * 256 + tid;            // float4 index, 0..2047
            int row = f >> 5;                 // 0..63
            int c4 = f & 31;                  // 0..31 (float4 within row)
            float4 v = *(const float4*)(x + (size_t)(rowbase + row) * CC + c4 * 4);
            __half2 h01 = __floats2half2_rn(v.x, v.y);
            __half2 h23 = __floats2half2_rn(v.z, v.w);
            uint32_t hw0 = *reinterpret_cast<uint32_t*>(&h01);
            uint32_t hw1 = *reinterpret_cast<uint32_t*>(&h23);
            uint32_t off = row * ROWB + c4 * 8;
            asm volatile("st.shared.v2.b32 [%0], {%1, %2};"
                         :: "r"(sb + SM_A + off), "r"(hw0), "r"(hw1) : "memory");
        }
        __syncthreads();

        // ---- MMA: single plane x 8 k16-steps ----
        float acc[2][8][4];
        #pragma unroll
        for (int mi = 0; mi < 2; mi++)
            #pragma unroll
            for (int ni = 0; ni < 8; ni++)
                #pragma unroll
                for (int r = 0; r < 4; r++) acc[mi][ni][r] = 0.f;

        #pragma unroll
        for (int kk = 0; kk < 8; kk++) {
            const uint32_t kby = kk * 32;
            uint32_t a0[4], a1[4];
            LDSM_X4(a0[0], a0[1], a0[2], a0[3], a_base + kby);
            LDSM_X4(a1[0], a1[1], a1[2], a1[3], a_base + 16 * ROWB + kby);
            uint32_t b[4][4];
            #pragma unroll
            for (int j = 0; j < 4; j++)
                LDSM_X4(b[j][0], b[j][1], b[j][2], b[j][3], b_base + j * 16 * ROWB + kby);
            #pragma unroll
            for (int j = 0; j < 4; j++) {
                MMA16816(acc[0][2 * j + 0], a0[0], a0[1], a0[2], a0[3], b[j][0], b[j][1]);
                MMA16816(acc[0][2 * j + 1], a0[0], a0[1], a0[2], a0[3], b[j][2], b[j][3]);
                MMA16816(acc[1][2 * j + 0], a1[0], a1[1], a1[2], a1[3], b[j][0], b[j][1]);
                MMA16816(acc[1][2 * j + 1], a1[0], a1[1], a1[2], a1[3], b[j][2], b[j][3]);
            }
        }

        // ---- epilogue: cols<128 -> g_A fp32 (+bias); cols>=128 -> g_Ph fp16 ----
        {
            const float* sbias = (const float*)(smem + SM_BIAS);
            const int g = lane >> 2;
            const int t = lane & 3;
            #pragma unroll
            for (int mi = 0; mi < 2; mi++) {
                #pragma unroll
                for (int half = 0; half < 2; half++) {
                    const int m = rowbase + wr * 32 + mi * 16 + g + half * 8;
                    #pragma unroll
                    for (int ni = 0; ni < 8; ni++) {
                        const int col = wc * 64 + ni * 8 + t * 2;
                        float c0 = acc[mi][ni][half * 2 + 0];
                        float c1 = acc[mi][ni][half * 2 + 1];
                        if (col < OO) {
                            float2 o = make_float2(c0 + sbias[col], c1 + sbias[col + 1]);
                            *(float2*)(g_A + (size_t)m * OO + col) = o;
                        } else {
                            __half2 h = __floats2half2_rn(c0, c1);
                            *(__half2*)(g_Ph + (size_t)m * OO + (col - OO)) = h;
                        }
                    }
                }
            }
        }
        __syncthreads();   // A smem free before next tile's convert
    }
}

// ---------------------------------------------------------------------------
// Gather-max + elu epilogue. One warp per node; fp16 P rows (256B/row),
// 8 independent half2 max accumulators, 4 LDG.64 in flight per iteration.
// ---------------------------------------------------------------------------
__device__ __forceinline__ float elu1(float v) {
    return v > 0.f ? v : expm1f(v);
}

__global__ __launch_bounds__(256) void gather_kernel(const void* __restrict__ eidx,
                                                     float* __restrict__ out) {
    const int gw = (blockIdx.x * 256 + threadIdx.x) >> 5;   // node row (b*N+n)
    const int lane = threadIdx.x & 31;
    if (gw >= BN) return;

    const int b = gw / NN;
    const int bbase = b * NN;

    const float4* __restrict__ A4 = (const float4*)g_A;
    const __half* __restrict__ Pb = g_Ph + (size_t)bbase * OO + lane * 4;

    int myidx;
    if (g_idx64) {
        myidx = (int)((const long long*)eidx)[(size_t)gw * EE + lane];
    } else {
        myidx = ((const int*)eidx)[(size_t)gw * EE + lane];
    }
    const unsigned vm = __ballot_sync(0xffffffffu, myidx >= 0);

    float4 a = A4[(size_t)gw * 32 + lane];   // prefetch early

    const __half2 ninf2 = __floats2half2_rn(-INFINITY, -INFINITY);
    __half2 m0a = ninf2, m0b = ninf2, m1a = ninf2, m1b = ninf2;
    __half2 m2a = ninf2, m2b = ninf2, m3a = ninf2, m3b = ninf2;

    #pragma unroll
    for (int e = 0; e < EE; e += 4) {
        int j0 = __shfl_sync(0xffffffffu, myidx, e + 0);
        int j1 = __shfl_sync(0xffffffffu, myidx, e + 1);
        int j2 = __shfl_sync(0xffffffffu, myidx, e + 2);
        int j3 = __shfl_sync(0xffffffffu, myidx, e + 3);
        if (j0 >= 0) {
            uint2 r = *(const uint2*)(Pb + (size_t)j0 * OO);
            m0a = __hmax2(m0a, *reinterpret_cast<__half2*>(&r.x));
            m0b = __hmax2(m0b, *reinterpret_cast<__half2*>(&r.y));
        }
        if (j1 >= 0) {
            uint2 r = *(const uint2*)(Pb + (size_t)j1 * OO);
            m1a = __hmax2(m1a, *reinterpret_cast<__half2*>(&r.x));
            m1b = __hmax2(m1b, *reinterpret_cast<__half2*>(&r.y));
        }
        if (j2 >= 0) {
            uint2 r = *(const uint2*)(Pb + (size_t)j2 * OO);
            m2a = __hmax2(m2a, *reinterpret_cast<__half2*>(&r.x));
            m2b = __hmax2(m2b, *reinterpret_cast<__half2*>(&r.y));
        }
        if (j3 >= 0) {
            uint2 r = *(const uint2*)(Pb + (size_t)j3 * OO);
            m3a = __hmax2(m3a, *reinterpret_cast<__half2*>(&r.x));
            m3b = __hmax2(m3b, *reinterpret_cast<__half2*>(&r.y));
        }
    }
    m0a = __hmax2(__hmax2(m0a, m1a), __hmax2(m2a, m3a));
    m0b = __hmax2(__hmax2(m0b, m1b), __hmax2(m2b, m3b));

    float4 o;
    if (vm == 0u) {
        o = make_float4(-INFINITY, -INFINITY, -INFINITY, -INFINITY);
    } else {
        float2 fa = __half22float2(m0a);
        float2 fb = __half22float2(m0b);
        o.x = elu1(a.x + fa.x);
        o.y = elu1(a.y + fa.y);
        o.z = elu1(a.z + fb.x);
        o.w = elu1(a.w + fb.y);
    }
    reinterpret_cast<float4*>(out)[(size_t)gw * 32 + lane] = o;
}

// ---------------------------------------------------------------------------
// Launch
// ---------------------------------------------------------------------------
extern "C" void kernel_launch(void* const* d_in, const int* in_sizes, int n_in,
                              void* d_out, int out_size) {
    (void)in_sizes; (void)n_in; (void)out_size;
    const float* x    = (const float*)d_in[0];   // [B,N,C] fp32
    const void*  eidx = d_in[1];                 // [B,N,E] int64 or int32
    const float* W    = (const float*)d_in[2];   // [2C,O] fp32
    const float* bias = (const float*)d_in[3];   // [O] fp32
    float* out = (float*)d_out;                  // [B,N,O] fp32

    cudaFuncSetAttribute(gemm_kernel, cudaFuncAttributeMaxDynamicSharedMemorySize, SMEM_SZ);

    prep_kernel<<<33, 256>>>(W, (const int*)eidx);
    gemm_kernel<<<GEMM_GRID, 256, SMEM_SZ>>>(x, bias);
    gather_kernel<<<BN / 8, 256>>>(eidx, out);
}